// round 1
// baseline (speedup 1.0000x reference)
#include <cuda_runtime.h>
#include <math.h>

// Problem dims
#define Bb 128
#define Ss 128
#define Nn 196
#define Dd 512
#define D2 1024
#define Tt 12

// ---------------- device scratch (no allocation allowed) ----------------
__device__ float g_p [Bb * Tt * Dd];   // all p_t precomputed  [B, T*D]
__device__ float g_u [Bb * Dd];        // (cc + bcq) * Wca
__device__ float g_c [Bb * Dd];        // control state
__device__ float g_m0[Bb * Dd];        // memory state double-buffer
__device__ float g_m1[Bb * Dd];
__device__ float g_mm[Bb * Dd];        // m @ Wrm^T + brm
__device__ float g_w2[Bb * D2];        // (c*Wra) @ Wrc
__device__ float g_r [Bb * Dd];        // read vector

// ---------------- helpers ----------------
__device__ __forceinline__ float warp_sum(float v) {
#pragma unroll
    for (int o = 16; o; o >>= 1) v += __shfl_xor_sync(0xffffffffu, v, o);
    return v;
}
__device__ __forceinline__ float warp_max(float v) {
#pragma unroll
    for (int o = 16; o; o >>= 1) v = fmaxf(v, __shfl_xor_sync(0xffffffffu, v, o));
    return v;
}

// ---------------- init: broadcast ctrl0/mem0 ----------------
__global__ void init_state(const float* __restrict__ ctrl0, const float* __restrict__ mem0) {
    int i = blockIdx.x * blockDim.x + threadIdx.x;      // 0..B*D-1
    int d = i & (Dd - 1);
    g_c[i]  = ctrl0[d];
    g_m0[i] = mem0[d];
}

// ---------------- generic fp32 GEMM: C[M,N] = concat(A0,A1)[M,K] * B^T + bias ----
// B element (n,k) = Bm[n*strideN + k*strideK]. strideK==1 -> NT (row-major [N,K]),
// strideN==1 -> NN (row-major [K,N]).
// Optional: kscale applied to A columns, nscale applied to output columns.
// Tiles: BM=32, BN=64, BK=32, 256 threads, 4x2 outputs/thread.
__global__ void gemm_nt(const float* __restrict__ A0, int lda0, int K0,
                        const float* __restrict__ A1, int lda1,
                        const float* __restrict__ Bm, int strideN, int strideK,
                        const float* __restrict__ bias,
                        const float* __restrict__ kscale,
                        const float* __restrict__ nscale,
                        float* __restrict__ C, int ldc, int K)
{
    __shared__ float As[32][33];
    __shared__ float Bs[32][65];
    const int tid = threadIdx.x;
    const int tm = tid >> 5;          // 0..7
    const int tn = tid & 31;          // 0..31
    const int bm = blockIdx.y * 32;
    const int bn = blockIdx.x * 64;

    float acc[4][2] = {};

    for (int k0 = 0; k0 < K; k0 += 32) {
        // A tile 32x32, store transposed As[k][m]
#pragma unroll
        for (int i = 0; i < 4; i++) {
            int idx = tid + i * 256;
            int r = idx >> 5, kk = idx & 31;
            int gk = k0 + kk;
            float v = (gk < K0) ? A0[(size_t)(bm + r) * lda0 + gk]
                                : A1[(size_t)(bm + r) * lda1 + (gk - K0)];
            if (kscale) v *= kscale[gk];
            As[kk][r] = v;
        }
        // B tile 64x32, store Bs[k][n]
        if (strideK == 1) {           // NT layout
#pragma unroll
            for (int i = 0; i < 8; i++) {
                int idx = tid + i * 256;
                int r = idx >> 5, kk = idx & 31;
                Bs[kk][r] = Bm[(size_t)(bn + r) * strideN + k0 + kk];
            }
        } else {                      // NN layout
#pragma unroll
            for (int i = 0; i < 8; i++) {
                int idx = tid + i * 256;
                int kk = idx >> 6, n = idx & 63;
                Bs[kk][n] = Bm[(size_t)(k0 + kk) * strideK + bn + n];
            }
        }
        __syncthreads();
#pragma unroll
        for (int kk = 0; kk < 32; kk++) {
            float a[4], bb[2];
#pragma unroll
            for (int i = 0; i < 4; i++) a[i] = As[kk][tm + 8 * i];
#pragma unroll
            for (int j = 0; j < 2; j++) bb[j] = Bs[kk][tn + 32 * j];
#pragma unroll
            for (int i = 0; i < 4; i++)
#pragma unroll
                for (int j = 0; j < 2; j++) acc[i][j] += a[i] * bb[j];
        }
        __syncthreads();
    }
#pragma unroll
    for (int i = 0; i < 4; i++) {
        int m = bm + tm + 8 * i;
#pragma unroll
        for (int j = 0; j < 2; j++) {
            int n = bn + tn + 32 * j;
            float v = acc[i][j];
            if (bias)   v += bias[n];
            if (nscale) v *= nscale[n];
            C[(size_t)m * ldc + n] = v;
        }
    }
}

// ---------------- ctx attention: logits over S, softmax, weighted sum -> g_c ---
// one block per batch row, 512 threads
__global__ void attn_ctx(const float* __restrict__ ctx) {
    __shared__ float us[Dd];
    __shared__ float sl[Ss];
    __shared__ float red;
    const int b = blockIdx.x;
    const int tid = threadIdx.x;
    const int lane = tid & 31, warp = tid >> 5;

    us[tid] = g_u[b * Dd + tid];
    __syncthreads();

    const float* cb = ctx + (size_t)b * Ss * Dd;
    // pass 1: logits
    for (int s = warp; s < Ss; s += 16) {
        const float* row = cb + (size_t)s * Dd;
        float part = 0.f;
#pragma unroll 4
        for (int d = lane; d < Dd; d += 32) part += us[d] * row[d];
        part = warp_sum(part);
        if (lane == 0) sl[s] = part;
    }
    __syncthreads();
    // softmax over S=128 (warp 0)
    if (warp == 0) {
        float mx = -1e30f;
        for (int i = lane; i < Ss; i += 32) mx = fmaxf(mx, sl[i]);
        mx = warp_max(mx);
        float sm = 0.f;
        for (int i = lane; i < Ss; i += 32) { float e = __expf(sl[i] - mx); sl[i] = e; sm += e; }
        sm = warp_sum(sm);
        if (lane == 0) red = 1.f / sm;
    }
    __syncthreads();
    const float inv = red;
    // pass 2: c[d] = sum_s w[s]*ctx[b,s,d]
    float acc = 0.f;
#pragma unroll 4
    for (int s = 0; s < Ss; s++) acc += sl[s] * cb[(size_t)s * Dd + tid];
    g_c[b * Dd + tid] = acc * inv;
}

// ---------------- k attention: logits over N, softmax, weighted sum -> g_r -----
// one block per batch row, 512 threads
__global__ void attn_k(const float* __restrict__ kp) {
    __shared__ float gs[Dd];
    __shared__ float rw[Nn];
    __shared__ float red;
    const int b = blockIdx.x;
    const int tid = threadIdx.x;
    const int lane = tid & 31, warp = tid >> 5;

    gs[tid] = g_w2[b * D2 + tid] * g_mm[b * Dd + tid] + g_w2[b * D2 + Dd + tid];
    __syncthreads();

    const float* kb = kp + (size_t)b * Dd * Nn;
    // pass 1: logits (thread per n, coalesced over n)
    if (tid < Nn) {
        float acc = 0.f;
#pragma unroll 8
        for (int j = 0; j < Dd; j++) acc += gs[j] * kb[(size_t)j * Nn + tid];
        rw[tid] = acc;
    }
    __syncthreads();
    if (warp == 0) {
        float mx = -1e30f;
        for (int i = lane; i < Nn; i += 32) mx = fmaxf(mx, rw[i]);
        mx = warp_max(mx);
        float sm = 0.f;
        for (int i = lane; i < Nn; i += 32) { float e = __expf(rw[i] - mx); rw[i] = e; sm += e; }
        sm = warp_sum(sm);
        if (lane == 0) red = 1.f / sm;
    }
    __syncthreads();
    const float inv = red;
    // pass 2: r[d] = sum_n w[n]*k[b,d,n]  (warp per d, coalesced row reads)
    for (int d = warp; d < Dd; d += 16) {
        const float* row = kb + (size_t)d * Nn;
        float part = 0.f;
        for (int n = lane; n < Nn; n += 32) part += rw[n] * row[n];
        part = warp_sum(part);
        if (lane == 0) g_r[b * Dd + d] = part * inv;
    }
}

// ---------------- host ----------------
extern "C" void kernel_launch(void* const* d_in, const int* in_sizes, int n_in,
                              void* d_out, int out_size)
{
    const float* ctx  = (const float*)d_in[0];
    const float* q    = (const float*)d_in[1];
    const float* kten = (const float*)d_in[2];
    const float* mem0 = (const float*)d_in[3];
    const float* ctrl0= (const float*)d_in[4];
    const float* Wp   = (const float*)d_in[5];
    const float* bp   = (const float*)d_in[6];
    const float* Wcq  = (const float*)d_in[7];
    const float* bcq  = (const float*)d_in[8];
    const float* Wca  = (const float*)d_in[9];
    // d_in[10] = bca  : constant shift, cancels in softmax
    const float* Wrm  = (const float*)d_in[11];
    const float* brm  = (const float*)d_in[12];
    const float* Wrc  = (const float*)d_in[13];
    // d_in[14] = brc  : per-row constant in logits, cancels in softmax
    const float* Wra  = (const float*)d_in[15];
    // d_in[16] = bra  : cancels in softmax
    const float* Wwc  = (const float*)d_in[17];
    const float* bwc  = (const float*)d_in[18];
    float* out = (float*)d_out;

    float *p_, *u_, *c_, *m0_, *m1_, *mm_, *w2_, *r_;
    cudaGetSymbolAddress((void**)&p_,  g_p);
    cudaGetSymbolAddress((void**)&u_,  g_u);
    cudaGetSymbolAddress((void**)&c_,  g_c);
    cudaGetSymbolAddress((void**)&m0_, g_m0);
    cudaGetSymbolAddress((void**)&m1_, g_m1);
    cudaGetSymbolAddress((void**)&mm_, g_mm);
    cudaGetSymbolAddress((void**)&w2_, g_w2);
    cudaGetSymbolAddress((void**)&r_,  g_r);

    // init states
    init_state<<<(Bb * Dd) / 256, 256>>>(ctrl0, mem0);

    // precompute all p_t: [B, T*D] = q[B,2D] @ Wp[T*D,2D]^T + bp
    {
        dim3 grid((Tt * Dd) / 64, Bb / 32);
        gemm_nt<<<grid, 256>>>(q, D2, D2, nullptr, 0,
                               Wp, D2, 1, bp, nullptr, nullptr,
                               p_, Tt * Dd, D2);
    }

    dim3 g512(Dd / 64, Bb / 32);     // N=512
    dim3 g1024(D2 / 64, Bb / 32);    // N=1024

    for (int t = 0; t < Tt; t++) {
        float* m_in  = (t & 1) ? m1_ : m0_;
        float* m_out = (t & 1) ? m0_ : m1_;

        // u = ((concat(c, p_t) @ Wcq^T) + bcq) * Wca
        gemm_nt<<<g512, 256>>>(c_, Dd, Dd, p_ + t * Dd, Tt * Dd,
                               Wcq, D2, 1, bcq, nullptr, Wca,
                               u_, Dd, D2);
        // mm = m @ Wrm^T + brm   (independent of attn_ctx)
        gemm_nt<<<g512, 256>>>(m_in, Dd, Dd, nullptr, 0,
                               Wrm, Dd, 1, brm, nullptr, nullptr,
                               mm_, Dd, Dd);
        // ctx attention -> new c
        attn_ctx<<<Bb, Dd>>>(ctx);
        // w2 = (c * Wra) @ Wrc   (Wrc is [D,2D] row-major -> NN access)
        gemm_nt<<<g1024, 256>>>(c_, Dd, Dd, nullptr, 0,
                                Wrc, 1, D2, nullptr, Wra, nullptr,
                                w2_, D2, Dd);
        // k attention -> r
        attn_k<<<Bb, Dd>>>(kten);
        // m' = concat(r, m) @ Wwc^T + bwc
        float* cdst = (t == Tt - 1) ? out : m_out;
        gemm_nt<<<g512, 256>>>(r_, Dd, Dd, m_in, Dd,
                               Wwc, D2, 1, bwc, nullptr, nullptr,
                               cdst, Dd, D2);
    }
    (void)in_sizes; (void)n_in; (void)out_size;
}

// round 3
// speedup vs baseline: 2.5807x; 2.5807x over previous
#include <cuda_runtime.h>
#include <math.h>

// Problem dims
#define Bb 128
#define Ss 128
#define Nn 196
#define Dd 512
#define D2 1024
#define Tt 12
#define NCH 4          // split-K chunks for per-iteration GEMMs

// ---------------- device scratch ----------------
__device__ float g_p   [Bb * Tt * Dd];       // p_t for all t         [B, T*D]
__device__ float g_P2  [Bb * Tt * Dd];       // p @ Wcq2^T            [(B*T), D]
__device__ float g_up  [NCH * Bb * Dd];      // u partials
__device__ float g_w2p [NCH * Bb * D2];      // w2 partials
__device__ float g_fp  [NCH * Bb * D2];      // fused write partials
__device__ float g_Bcomb[D2 * D2];           // [Wwc ; Wrm@Wwc]       [1024,1024]
__device__ float g_c   [Bb * Dd];
__device__ float g_m   [Bb * Dd];            // reduced memory state
__device__ float g_mm  [Bb * Dd];            // m @ Wrm^T + brm (reduced)
__device__ float g_r   [Bb * Dd];
__device__ float g_bias2[Dd];                // brm + Wrm@bwc

// ---------------- helpers ----------------
__device__ __forceinline__ float warp_sum(float v) {
#pragma unroll
    for (int o = 16; o; o >>= 1) v += __shfl_xor_sync(0xffffffffu, v, o);
    return v;
}
__device__ __forceinline__ float warp_max(float v) {
#pragma unroll
    for (int o = 16; o; o >>= 1) v = fmaxf(v, __shfl_xor_sync(0xffffffffu, v, o));
    return v;
}

// ---------------- init ----------------
__global__ void init_state(const float* __restrict__ ctrl0, const float* __restrict__ mem0) {
    int i = blockIdx.x * blockDim.x + threadIdx.x;      // 0..B*D-1
    int d = i & (Dd - 1);
    g_c[i] = ctrl0[d];
    g_m[i] = mem0[d];
}

// bias2[i] = brm[i] + dot(Wrm[i,:], bwc); g_mm rows = brm + Wrm@mem0 (broadcast)
__global__ void prep_read(const float* __restrict__ Wrm, const float* __restrict__ brm,
                          const float* __restrict__ bwc, const float* __restrict__ mem0) {
    int w = (blockIdx.x * blockDim.x + threadIdx.x) >> 5;   // row 0..511
    int lane = threadIdx.x & 31;
    const float* row = Wrm + (size_t)w * Dd;
    float s1 = 0.f, s2 = 0.f;
    for (int d = lane; d < Dd; d += 32) { float x = row[d]; s1 += x * bwc[d]; s2 += x * mem0[d]; }
    s1 = warp_sum(s1); s2 = warp_sum(s2);
    float b2  = brm[w] + s1;
    float mm0 = brm[w] + s2;
    if (lane == 0) g_bias2[w] = b2;
    for (int b = lane; b < Bb; b += 32) g_mm[b * Dd + w] = mm0;
}

// ---------------- split-K GEMM ----------------
// C[M,N] = concat(A0,A1)[M,K] * B^T (+bias).  B(n,k) = Bm[n*strideN + k*strideK].
// gridDim.z==1 -> final write to Cfin (+bias). gridDim.z>1 -> partials to Part.
// Tiles: BM=32, BN=64, BK=32, 256 threads, register-prefetch double buffering.
__global__ __launch_bounds__(256) void gemm_sk(
    const float* __restrict__ A0, int lda0, int K0,
    const float* __restrict__ A1, int lda1,
    const float* __restrict__ Bm, int strideN, int strideK,
    const float* __restrict__ kscale,
    const float* __restrict__ bias,
    float* __restrict__ Cfin, int ldc,
    float* __restrict__ Part,
    int K)
{
    __shared__ float As[32][33];
    __shared__ float Bs[32][65];
    const int tid = threadIdx.x;
    const int tm = tid >> 5;          // 0..7
    const int tn = tid & 31;          // 0..31
    const int bm = blockIdx.y * 32;
    const int bn = blockIdx.x * 64;
    const int N  = gridDim.x * 64;
    const int kchunk = K / gridDim.z;
    const int kbeg = blockIdx.z * kchunk;
    const int kend = kbeg + kchunk;

    float acc[4][2] = {};
    float ra[4], rb[8];

    // prologue loads
#pragma unroll
    for (int i = 0; i < 4; i++) {
        int idx = tid + i * 256; int r = idx >> 5, kk = idx & 31;
        int gk = kbeg + kk;
        float v = (gk < K0) ? A0[(size_t)(bm + r) * lda0 + gk]
                            : A1[(size_t)(bm + r) * lda1 + (gk - K0)];
        if (kscale) v *= kscale[gk];
        ra[i] = v;
    }
    if (strideK == 1) {
#pragma unroll
        for (int i = 0; i < 8; i++) {
            int idx = tid + i * 256; int r = idx >> 5, kk = idx & 31;
            rb[i] = Bm[(size_t)(bn + r) * strideN + kbeg + kk];
        }
    } else {
#pragma unroll
        for (int i = 0; i < 8; i++) {
            int idx = tid + i * 256; int kk = idx >> 6, n = idx & 63;
            rb[i] = Bm[(size_t)(kbeg + kk) * strideK + bn + n];
        }
    }

    for (int k0 = kbeg; k0 < kend; k0 += 32) {
        // store current tile
#pragma unroll
        for (int i = 0; i < 4; i++) {
            int idx = tid + i * 256; int r = idx >> 5, kk = idx & 31;
            As[kk][r] = ra[i];
        }
        if (strideK == 1) {
#pragma unroll
            for (int i = 0; i < 8; i++) {
                int idx = tid + i * 256; int r = idx >> 5, kk = idx & 31;
                Bs[kk][r] = rb[i];
            }
        } else {
#pragma unroll
            for (int i = 0; i < 8; i++) {
                int idx = tid + i * 256; int kk = idx >> 6, n = idx & 63;
                Bs[kk][n] = rb[i];
            }
        }
        __syncthreads();

        // prefetch next tile into registers while computing
        if (k0 + 32 < kend) {
            int knext = k0 + 32;
#pragma unroll
            for (int i = 0; i < 4; i++) {
                int idx = tid + i * 256; int r = idx >> 5, kk = idx & 31;
                int gk = knext + kk;
                float v = (gk < K0) ? A0[(size_t)(bm + r) * lda0 + gk]
                                    : A1[(size_t)(bm + r) * lda1 + (gk - K0)];
                if (kscale) v *= kscale[gk];
                ra[i] = v;
            }
            if (strideK == 1) {
#pragma unroll
                for (int i = 0; i < 8; i++) {
                    int idx = tid + i * 256; int r = idx >> 5, kk = idx & 31;
                    rb[i] = Bm[(size_t)(bn + r) * strideN + knext + kk];
                }
            } else {
#pragma unroll
                for (int i = 0; i < 8; i++) {
                    int idx = tid + i * 256; int kk = idx >> 6, n = idx & 63;
                    rb[i] = Bm[(size_t)(knext + kk) * strideK + bn + n];
                }
            }
        }

#pragma unroll
        for (int kk = 0; kk < 32; kk++) {
            float a[4], bv[2];
#pragma unroll
            for (int i = 0; i < 4; i++) a[i] = As[kk][tm + 8 * i];
#pragma unroll
            for (int j = 0; j < 2; j++) bv[j] = Bs[kk][tn + 32 * j];
#pragma unroll
            for (int i = 0; i < 4; i++)
#pragma unroll
                for (int j = 0; j < 2; j++) acc[i][j] += a[i] * bv[j];
        }
        __syncthreads();
    }

    if (Part) {
        size_t base = (size_t)blockIdx.z * (size_t)(gridDim.y * 32) * N;
#pragma unroll
        for (int i = 0; i < 4; i++) {
            int m = bm + tm + 8 * i;
#pragma unroll
            for (int j = 0; j < 2; j++) {
                int n = bn + tn + 32 * j;
                Part[base + (size_t)m * N + n] = acc[i][j];
            }
        }
    } else {
#pragma unroll
        for (int i = 0; i < 4; i++) {
            int m = bm + tm + 8 * i;
#pragma unroll
            for (int j = 0; j < 2; j++) {
                int n = bn + tn + 32 * j;
                float v = acc[i][j];
                if (bias) v += bias[n];
                Cfin[(size_t)m * ldc + n] = v;
            }
        }
    }
}

// ---------------- reduce fused-write partials: m half + mm half ----------------
__global__ void reduce_f(const float* __restrict__ bwc, float* __restrict__ mdst) {
    int idx = blockIdx.x * blockDim.x + threadIdx.x;   // 0 .. B*1024-1
    int b = idx >> 10, j = idx & 1023;
    float v = g_fp[idx] + g_fp[Bb * D2 + idx] + g_fp[2 * Bb * D2 + idx] + g_fp[3 * Bb * D2 + idx];
    if (j < Dd) mdst[b * Dd + j]        = v + bwc[j];
    else        g_mm[b * Dd + (j - Dd)] = v + g_bias2[j - Dd];
}

// ---------------- ctx attention (reduces u partials, adds P2_t) ----------------
__global__ void attn_ctx(const float* __restrict__ ctx, const float* __restrict__ bcq,
                         const float* __restrict__ Wca, int t) {
    __shared__ float us[Dd];
    __shared__ float sl[Ss];
    __shared__ float red;
    const int b = blockIdx.x;
    const int tid = threadIdx.x;
    const int lane = tid & 31, warp = tid >> 5;

    {
        int o = b * Dd + tid;
        float v = g_up[o] + g_up[Bb * Dd + o] + g_up[2 * Bb * Dd + o] + g_up[3 * Bb * Dd + o];
        v += bcq[tid] + g_P2[(size_t)(b * Tt + t) * Dd + tid];
        us[tid] = v * Wca[tid];
    }
    __syncthreads();

    const float* cb = ctx + (size_t)b * Ss * Dd;
    for (int s = warp; s < Ss; s += 16) {
        const float* row = cb + (size_t)s * Dd;
        float part = 0.f;
#pragma unroll 4
        for (int d = lane; d < Dd; d += 32) part += us[d] * row[d];
        part = warp_sum(part);
        if (lane == 0) sl[s] = part;
    }
    __syncthreads();
    if (warp == 0) {
        float mx = -1e30f;
        for (int i = lane; i < Ss; i += 32) mx = fmaxf(mx, sl[i]);
        mx = warp_max(mx);
        float sm = 0.f;
        for (int i = lane; i < Ss; i += 32) { float e = __expf(sl[i] - mx); sl[i] = e; sm += e; }
        sm = warp_sum(sm);
        if (lane == 0) red = 1.f / sm;
    }
    __syncthreads();
    const float inv = red;
    float acc = 0.f;
#pragma unroll 4
    for (int s = 0; s < Ss; s++) acc += sl[s] * cb[(size_t)s * Dd + tid];
    g_c[b * Dd + tid] = acc * inv;
}

// ---------------- k attention (reduces w2 partials, uses g_mm) ----------------
__global__ void attn_k(const float* __restrict__ kp) {
    __shared__ float gs[Dd];
    __shared__ float rw[Nn];
    __shared__ float red;
    const int b = blockIdx.x;
    const int tid = threadIdx.x;
    const int lane = tid & 31, warp = tid >> 5;

    {
        int oa = b * D2 + tid;
        int ob = b * D2 + Dd + tid;
        float w2a = g_w2p[oa] + g_w2p[Bb * D2 + oa] + g_w2p[2 * Bb * D2 + oa] + g_w2p[3 * Bb * D2 + oa];
        float w2b = g_w2p[ob] + g_w2p[Bb * D2 + ob] + g_w2p[2 * Bb * D2 + ob] + g_w2p[3 * Bb * D2 + ob];
        gs[tid] = w2a * g_mm[b * Dd + tid] + w2b;
    }
    __syncthreads();

    const float* kb = kp + (size_t)b * Dd * Nn;
    if (tid < Nn) {
        float acc = 0.f;
#pragma unroll 8
        for (int j = 0; j < Dd; j++) acc += gs[j] * kb[(size_t)j * Nn + tid];
        rw[tid] = acc;
    }
    __syncthreads();
    if (warp == 0) {
        float mx = -1e30f;
        for (int i = lane; i < Nn; i += 32) mx = fmaxf(mx, rw[i]);
        mx = warp_max(mx);
        float sm = 0.f;
        for (int i = lane; i < Nn; i += 32) { float e = __expf(rw[i] - mx); rw[i] = e; sm += e; }
        sm = warp_sum(sm);
        if (lane == 0) red = 1.f / sm;
    }
    __syncthreads();
    const float inv = red;
    for (int d = warp; d < Dd; d += 16) {
        const float* row = kb + (size_t)d * Nn;
        float part = 0.f;
        for (int n = lane; n < Nn; n += 32) part += rw[n] * row[n];
        part = warp_sum(part);
        if (lane == 0) g_r[b * Dd + d] = part * inv;
    }
}

// ---------------- host ----------------
extern "C" void kernel_launch(void* const* d_in, const int* in_sizes, int n_in,
                              void* d_out, int out_size)
{
    const float* ctx  = (const float*)d_in[0];
    const float* q    = (const float*)d_in[1];
    const float* kten = (const float*)d_in[2];
    const float* mem0 = (const float*)d_in[3];
    const float* ctrl0= (const float*)d_in[4];
    const float* Wp   = (const float*)d_in[5];
    const float* bp   = (const float*)d_in[6];
    const float* Wcq  = (const float*)d_in[7];
    const float* bcq  = (const float*)d_in[8];
    const float* Wca  = (const float*)d_in[9];
    // d_in[10] = bca : cancels in softmax
    const float* Wrm  = (const float*)d_in[11];
    const float* brm  = (const float*)d_in[12];
    const float* Wrc  = (const float*)d_in[13];
    // d_in[14] = brc : cancels in softmax
    const float* Wra  = (const float*)d_in[15];
    // d_in[16] = bra : cancels in softmax
    const float* Wwc  = (const float*)d_in[17];
    const float* bwc  = (const float*)d_in[18];
    float* out = (float*)d_out;

    float *p_, *P2_, *up_, *w2p_, *fp_, *Bc_, *c_, *m_, *r_;
    cudaGetSymbolAddress((void**)&p_,   g_p);
    cudaGetSymbolAddress((void**)&P2_,  g_P2);
    cudaGetSymbolAddress((void**)&up_,  g_up);
    cudaGetSymbolAddress((void**)&w2p_, g_w2p);
    cudaGetSymbolAddress((void**)&fp_,  g_fp);
    cudaGetSymbolAddress((void**)&Bc_,  g_Bcomb);
    cudaGetSymbolAddress((void**)&c_,   g_c);
    cudaGetSymbolAddress((void**)&m_,   g_m);
    cudaGetSymbolAddress((void**)&r_,   g_r);

    // --- setup ---
    init_state<<<(Bb * Dd) / 256, 256>>>(ctrl0, mem0);
    prep_read<<<64, 256>>>(Wrm, brm, bwc, mem0);
    // Bcomb top half = Wwc
    cudaMemcpyAsync(Bc_, Wwc, (size_t)Dd * D2 * sizeof(float), cudaMemcpyDeviceToDevice, 0);
    // Bcomb bottom half = Wrm @ Wwc  (M=512, N=1024, K=512, NN B access)
    gemm_sk<<<dim3(16, 16, 1), 256>>>(Wrm, Dd, Dd, nullptr, 0,
                                      Wwc, 1, D2, nullptr, nullptr,
                                      Bc_ + (size_t)Dd * D2, D2, nullptr, Dd);
    // p = q @ Wp^T + bp   (M=128, N=6144, K=1024)
    gemm_sk<<<dim3(96, 4, 1), 256>>>(q, D2, D2, nullptr, 0,
                                     Wp, D2, 1, nullptr, bp,
                                     p_, Tt * Dd, nullptr, D2);
    // P2 = p(viewed [1536,512]) @ Wcq2^T   (M=1536, N=512, K=512)
    gemm_sk<<<dim3(8, 48, 1), 256>>>(p_, Dd, Dd, nullptr, 0,
                                     Wcq + Dd, D2, 1, nullptr, nullptr,
                                     P2_, Dd, nullptr, Dd);

    for (int t = 0; t < Tt; t++) {
        if (t > 0) reduce_f<<<(Bb * D2) / 256, 256>>>(bwc, m_);
        // u partials: c @ Wcq1^T   (M=128, N=512, K=512, split-K 4)
        gemm_sk<<<dim3(8, 4, NCH), 256>>>(c_, Dd, Dd, nullptr, 0,
                                          Wcq, D2, 1, nullptr, nullptr,
                                          nullptr, 0, up_, Dd);
        attn_ctx<<<Bb, Dd>>>(ctx, bcq, Wca, t);
        // w2 partials: (c*Wra) @ Wrc   (M=128, N=1024, K=512, split-K 4, NN B)
        gemm_sk<<<dim3(16, 4, NCH), 256>>>(c_, Dd, Dd, nullptr, 0,
                                           Wrc, 1, D2, Wra, nullptr,
                                           nullptr, 0, w2p_, Dd);
        attn_k<<<Bb, Dd>>>(kten);
        // fused write partials: concat(r, m) @ Bcomb^T  (M=128, N=1024, K=1024, split-K 4)
        gemm_sk<<<dim3(16, 4, NCH), 256>>>(r_, Dd, Dd, m_, Dd,
                                           Bc_, D2, 1, nullptr, nullptr,
                                           nullptr, 0, fp_, D2);
    }
    // final m -> out
    reduce_f<<<(Bb * D2) / 256, 256>>>(bwc, out);

    (void)in_sizes; (void)n_in; (void)out_size;
}

// round 6
// speedup vs baseline: 2.6806x; 1.0387x over previous
#include <cuda_runtime.h>
#include <math.h>

// Problem dims
#define Bb 128
#define Ss 128
#define Nn 196
#define Dd 512
#define D2 1024
#define Tt 12
#define NCH 4          // split-K chunks for w2 / write GEMMs
#define NCHU 8         // split-K chunks for u GEMM

// ---------------- device scratch ----------------
__device__ float g_p   [Bb * Tt * Dd];       // p_t for all t         [B, T*D]
__device__ float g_P2  [Bb * Tt * Dd];       // p @ Wcq2^T            [(B*T), D]
__device__ float g_up  [NCHU * Bb * Dd];     // u partials
__device__ float g_w2p [NCH * Bb * D2];      // w2 partials
__device__ float g_fp  [NCH * Bb * D2];      // fused write partials
__device__ float g_Bcomb[D2 * D2];           // [Wwc ; Wrm@Wwc]       [1024,1024]
__device__ float g_c   [Bb * Dd];
__device__ float g_m   [Bb * Dd];            // reduced memory state
__device__ float g_mm  [Bb * Dd];            // m @ Wrm^T + brm (reduced)
__device__ float g_r   [Bb * Dd];
__device__ float g_bias2[Dd];                // brm + Wrm@bwc

// ---------------- helpers ----------------
__device__ __forceinline__ float warp_sum(float v) {
#pragma unroll
    for (int o = 16; o; o >>= 1) v += __shfl_xor_sync(0xffffffffu, v, o);
    return v;
}
__device__ __forceinline__ float warp_max(float v) {
#pragma unroll
    for (int o = 16; o; o >>= 1) v = fmaxf(v, __shfl_xor_sync(0xffffffffu, v, o));
    return v;
}

// ---------------- init ----------------
__global__ void init_state(const float* __restrict__ ctrl0, const float* __restrict__ mem0) {
    int i = blockIdx.x * blockDim.x + threadIdx.x;
    int d = i & (Dd - 1);
    g_c[i] = ctrl0[d];
    g_m[i] = mem0[d];
}

__global__ void prep_read(const float* __restrict__ Wrm, const float* __restrict__ brm,
                          const float* __restrict__ bwc, const float* __restrict__ mem0) {
    int w = (blockIdx.x * blockDim.x + threadIdx.x) >> 5;
    int lane = threadIdx.x & 31;
    const float* row = Wrm + (size_t)w * Dd;
    float s1 = 0.f, s2 = 0.f;
    for (int d = lane; d < Dd; d += 32) { float x = row[d]; s1 += x * bwc[d]; s2 += x * mem0[d]; }
    s1 = warp_sum(s1); s2 = warp_sum(s2);
    float b2  = brm[w] + s1;
    float mm0 = brm[w] + s2;
    if (lane == 0) g_bias2[w] = b2;
    for (int b = lane; b < Bb; b += 32) g_mm[b * Dd + w] = mm0;
}

// ---------------- vectorized split-K GEMM ----------------
// C[M,N] = concat(A0,A1)[M,K] * B^T (+bias).  B(n,k) = Bm[n*strideN + k*strideK].
// BM=64, BN=64, BK=16, 256 threads, 4x4 outputs/thread, LDS.128 operands.
// gridDim.z==1 -> final write to Cfin (+bias); else partials to Part.
// Requires: K0 % 4 == 0, lda % 4 == 0, kchunk % 16 == 0, M % 64 == 0, N % 64 == 0.
__global__ __launch_bounds__(256) void gemm_sk(
    const float* __restrict__ A0, int lda0, int K0,
    const float* __restrict__ A1, int lda1,
    const float* __restrict__ Bm, int strideN, int strideK,
    const float* __restrict__ kscale,
    const float* __restrict__ bias,
    float* __restrict__ Cfin, int ldc,
    float* __restrict__ Part,
    int K)
{
    __shared__ __align__(16) float As[16][68];
    __shared__ __align__(16) float Bs[16][68];
    const int tid = threadIdx.x;
    const int ty = tid >> 4;            // 0..15
    const int tx = tid & 15;            // 0..15
    const int bm = blockIdx.y * 64;
    const int bn = blockIdx.x * 64;
    const int N  = gridDim.x * 64;
    const int kchunk = K / gridDim.z;
    const int kbeg = blockIdx.z * kchunk;
    const int kend = kbeg + kchunk;

    const int aRow = tid >> 2, aKq = tid & 3;      // A / B-NT load mapping
    const int bKk = tid >> 4, bNx = tid & 15;      // B-NN load mapping
    const bool nt = (strideK == 1);

    float acc[4][4] = {};
    float4 ra, rb;

    // ---- prologue loads (tile kbeg) ----
    {
        int gk = kbeg + aKq * 4;
        const float* src = (gk < K0) ? (A0 + (size_t)(bm + aRow) * lda0 + gk)
                                     : (A1 + (size_t)(bm + aRow) * lda1 + (gk - K0));
        ra = *(const float4*)src;
        if (kscale) {
            float4 ks = *(const float4*)(kscale + gk);
            ra.x *= ks.x; ra.y *= ks.y; ra.z *= ks.z; ra.w *= ks.w;
        }
        if (nt)  rb = *(const float4*)(Bm + (size_t)(bn + aRow) * strideN + kbeg + aKq * 4);
        else     rb = *(const float4*)(Bm + (size_t)(kbeg + bKk) * strideK + bn + bNx * 4);
    }

    for (int k0 = kbeg; k0 < kend; k0 += 16) {
        // store current tile (A transposed scatter; B per layout)
        As[aKq * 4 + 0][aRow] = ra.x;
        As[aKq * 4 + 1][aRow] = ra.y;
        As[aKq * 4 + 2][aRow] = ra.z;
        As[aKq * 4 + 3][aRow] = ra.w;
        if (nt) {
            Bs[aKq * 4 + 0][aRow] = rb.x;
            Bs[aKq * 4 + 1][aRow] = rb.y;
            Bs[aKq * 4 + 2][aRow] = rb.z;
            Bs[aKq * 4 + 3][aRow] = rb.w;
        } else {
            *(float4*)&Bs[bKk][bNx * 4] = rb;
        }
        __syncthreads();

        // prefetch next tile
        if (k0 + 16 < kend) {
            int kn = k0 + 16;
            int gk = kn + aKq * 4;
            const float* src = (gk < K0) ? (A0 + (size_t)(bm + aRow) * lda0 + gk)
                                         : (A1 + (size_t)(bm + aRow) * lda1 + (gk - K0));
            ra = *(const float4*)src;
            if (kscale) {
                float4 ks = *(const float4*)(kscale + gk);
                ra.x *= ks.x; ra.y *= ks.y; ra.z *= ks.z; ra.w *= ks.w;
            }
            if (nt)  rb = *(const float4*)(Bm + (size_t)(bn + aRow) * strideN + kn + aKq * 4);
            else     rb = *(const float4*)(Bm + (size_t)(kn + bKk) * strideK + bn + bNx * 4);
        }

#pragma unroll
        for (int kk = 0; kk < 16; kk++) {
            float4 a = *(const float4*)&As[kk][ty * 4];
            float4 b = *(const float4*)&Bs[kk][tx * 4];
            float av[4] = {a.x, a.y, a.z, a.w};
            float bv[4] = {b.x, b.y, b.z, b.w};
#pragma unroll
            for (int i = 0; i < 4; i++)
#pragma unroll
                for (int j = 0; j < 4; j++) acc[i][j] += av[i] * bv[j];
        }
        __syncthreads();
    }

    if (Part) {
        size_t base = (size_t)blockIdx.z * (size_t)(gridDim.y * 64) * N;
#pragma unroll
        for (int i = 0; i < 4; i++) {
            int m = bm + ty * 4 + i;
            float4 v = make_float4(acc[i][0], acc[i][1], acc[i][2], acc[i][3]);
            *(float4*)&Part[base + (size_t)m * N + bn + tx * 4] = v;
        }
    } else {
        float4 bz = make_float4(0.f, 0.f, 0.f, 0.f);
        if (bias) bz = *(const float4*)(bias + bn + tx * 4);
#pragma unroll
        for (int i = 0; i < 4; i++) {
            int m = bm + ty * 4 + i;
            float4 v = make_float4(acc[i][0] + bz.x, acc[i][1] + bz.y,
                                   acc[i][2] + bz.z, acc[i][3] + bz.w);
            *(float4*)&Cfin[(size_t)m * ldc + bn + tx * 4] = v;
        }
    }
}

// ---------------- reduce fused-write partials: m half + mm half ----------------
__global__ void reduce_f(const float* __restrict__ bwc, float* __restrict__ mdst) {
    int idx = blockIdx.x * blockDim.x + threadIdx.x;
    int b = idx >> 10, j = idx & 1023;
    float v = g_fp[idx] + g_fp[Bb * D2 + idx] + g_fp[2 * Bb * D2 + idx] + g_fp[3 * Bb * D2 + idx];
    if (j < Dd) mdst[b * Dd + j]        = v + bwc[j];
    else        g_mm[b * Dd + (j - Dd)] = v + g_bias2[j - Dd];
}

// ---------------- ctx attention (reduces u partials, adds P2_t) ----------------
__global__ void attn_ctx(const float* __restrict__ ctx, const float* __restrict__ bcq,
                         const float* __restrict__ Wca, int t) {
    __shared__ __align__(16) float us[Dd];
    __shared__ float sl[Ss];
    __shared__ float red;
    const int b = blockIdx.x;
    const int tid = threadIdx.x;
    const int lane = tid & 31, warp = tid >> 5;

    {
        int o = b * Dd + tid;
        float v = 0.f;
#pragma unroll
        for (int z = 0; z < NCHU; z++) v += g_up[z * Bb * Dd + o];
        v += bcq[tid] + g_P2[(size_t)(b * Tt + t) * Dd + tid];
        us[tid] = v * Wca[tid];
    }
    __syncthreads();

    const float* cb = ctx + (size_t)b * Ss * Dd;
    const float4* us4 = (const float4*)us;
    for (int s = warp; s < Ss; s += 16) {
        const float4* row4 = (const float4*)(cb + (size_t)s * Dd);
        float part = 0.f;
#pragma unroll
        for (int d4 = lane; d4 < Dd / 4; d4 += 32) {
            float4 a = row4[d4], u = us4[d4];
            part += a.x * u.x + a.y * u.y + a.z * u.z + a.w * u.w;
        }
        part = warp_sum(part);
        if (lane == 0) sl[s] = part;
    }
    __syncthreads();
    if (warp == 0) {
        float mx = -1e30f;
        for (int i = lane; i < Ss; i += 32) mx = fmaxf(mx, sl[i]);
        mx = warp_max(mx);
        float sm = 0.f;
        for (int i = lane; i < Ss; i += 32) { float e = __expf(sl[i] - mx); sl[i] = e; sm += e; }
        sm = warp_sum(sm);
        if (lane == 0) red = 1.f / sm;
    }
    __syncthreads();
    const float inv = red;
    float acc = 0.f;
#pragma unroll 8
    for (int s = 0; s < Ss; s++) acc += sl[s] * cb[(size_t)s * Dd + tid];
    g_c[b * Dd + tid] = acc * inv;
}

// ---------------- k attention (reduces w2 partials, uses g_mm) ----------------
__global__ void attn_k(const float* __restrict__ kp) {
    __shared__ float gs[Dd];
    __shared__ float rw[Nn];
    __shared__ float red;
    const int b = blockIdx.x;
    const int tid = threadIdx.x;
    const int lane = tid & 31, warp = tid >> 5;

    {
        int oa = b * D2 + tid;
        int ob = b * D2 + Dd + tid;
        float w2a = g_w2p[oa] + g_w2p[Bb * D2 + oa] + g_w2p[2 * Bb * D2 + oa] + g_w2p[3 * Bb * D2 + oa];
        float w2b = g_w2p[ob] + g_w2p[Bb * D2 + ob] + g_w2p[2 * Bb * D2 + ob] + g_w2p[3 * Bb * D2 + ob];
        gs[tid] = w2a * g_mm[b * Dd + tid] + w2b;
    }
    __syncthreads();

    const float* kb = kp + (size_t)b * Dd * Nn;
    if (tid < Nn) {
        float acc = 0.f;
#pragma unroll 8
        for (int j = 0; j < Dd; j++) acc += gs[j] * kb[(size_t)j * Nn + tid];
        rw[tid] = acc;
    }
    __syncthreads();
    if (warp == 0) {
        float mx = -1e30f;
        for (int i = lane; i < Nn; i += 32) mx = fmaxf(mx, rw[i]);
        mx = warp_max(mx);
        float sm = 0.f;
        for (int i = lane; i < Nn; i += 32) { float e = __expf(rw[i] - mx); rw[i] = e; sm += e; }
        sm = warp_sum(sm);
        if (lane == 0) red = 1.f / sm;
    }
    __syncthreads();
    const float inv = red;
    for (int d = warp; d < Dd; d += 16) {
        const float* row = kb + (size_t)d * Nn;
        float part = 0.f;
        for (int n = lane; n < Nn; n += 32) part += rw[n] * row[n];
        part = warp_sum(part);
        if (lane == 0) g_r[b * Dd + d] = part * inv;
    }
}

// ---------------- host ----------------
extern "C" void kernel_launch(void* const* d_in, const int* in_sizes, int n_in,
                              void* d_out, int out_size)
{
    const float* ctx  = (const float*)d_in[0];
    const float* q    = (const float*)d_in[1];
    const float* kten = (const float*)d_in[2];
    const float* mem0 = (const float*)d_in[3];
    const float* ctrl0= (const float*)d_in[4];
    const float* Wp   = (const float*)d_in[5];
    const float* bp   = (const float*)d_in[6];
    const float* Wcq  = (const float*)d_in[7];
    const float* bcq  = (const float*)d_in[8];
    const float* Wca  = (const float*)d_in[9];
    const float* Wrm  = (const float*)d_in[11];
    const float* brm  = (const float*)d_in[12];
    const float* Wrc  = (const float*)d_in[13];
    const float* Wra  = (const float*)d_in[15];
    const float* Wwc  = (const float*)d_in[17];
    const float* bwc  = (const float*)d_in[18];
    float* out = (float*)d_out;

    float *p_, *P2_, *up_, *w2p_, *fp_, *Bc_, *c_, *m_, *r_;
    cudaGetSymbolAddress((void**)&p_,   g_p);
    cudaGetSymbolAddress((void**)&P2_,  g_P2);
    cudaGetSymbolAddress((void**)&up_,  g_up);
    cudaGetSymbolAddress((void**)&w2p_, g_w2p);
    cudaGetSymbolAddress((void**)&fp_,  g_fp);
    cudaGetSymbolAddress((void**)&Bc_,  g_Bcomb);
    cudaGetSymbolAddress((void**)&c_,   g_c);
    cudaGetSymbolAddress((void**)&m_,   g_m);
    cudaGetSymbolAddress((void**)&r_,   g_r);

    // --- setup ---
    init_state<<<(Bb * Dd) / 256, 256>>>(ctrl0, mem0);
    prep_read<<<64, 256>>>(Wrm, brm, bwc, mem0);
    cudaMemcpyAsync(Bc_, Wwc, (size_t)Dd * D2 * sizeof(float), cudaMemcpyDeviceToDevice, 0);
    // Bcomb bottom = Wrm @ Wwc  (M=512, N=1024, K=512, NN)
    gemm_sk<<<dim3(16, 8, 1), 256>>>(Wrm, Dd, Dd, nullptr, 0,
                                     Wwc, 1, D2, nullptr, nullptr,
                                     Bc_ + (size_t)Dd * D2, D2, nullptr, Dd);
    // p = q @ Wp^T + bp   (M=128, N=6144, K=1024)
    gemm_sk<<<dim3(96, 2, 1), 256>>>(q, D2, D2, nullptr, 0,
                                     Wp, D2, 1, nullptr, bp,
                                     p_, Tt * Dd, nullptr, D2);
    // P2 = p(viewed [1536,512]) @ Wcq2^T   (M=1536, N=512, K=512)
    gemm_sk<<<dim3(8, 24, 1), 256>>>(p_, Dd, Dd, nullptr, 0,
                                     Wcq + Dd, D2, 1, nullptr, nullptr,
                                     P2_, Dd, nullptr, Dd);

    for (int t = 0; t < Tt; t++) {
        if (t > 0) reduce_f<<<(Bb * D2) / 256, 256>>>(bwc, m_);
        // u partials: c @ Wcq1^T   (M=128, N=512, K=512, split-K 8)
        gemm_sk<<<dim3(8, 2, NCHU), 256>>>(c_, Dd, Dd, nullptr, 0,
                                           Wcq, D2, 1, nullptr, nullptr,
                                           nullptr, 0, up_, Dd);
        attn_ctx<<<Bb, Dd>>>(ctx, bcq, Wca, t);
        // w2 partials: (c*Wra) @ Wrc   (M=128, N=1024, K=512, split-K 4, NN)
        gemm_sk<<<dim3(16, 2, NCH), 256>>>(c_, Dd, Dd, nullptr, 0,
                                           Wrc, 1, D2, Wra, nullptr,
                                           nullptr, 0, w2p_, Dd);
        attn_k<<<Bb, Dd>>>(kten);
        // fused write partials: concat(r, m) @ Bcomb^T  (M=128, N=1024, K=1024, split-K 4)
        gemm_sk<<<dim3(16, 2, NCH), 256>>>(r_, Dd, Dd, m_, Dd,
                                           Bc_, D2, 1, nullptr, nullptr,
                                           nullptr, 0, fp_, D2);
    }
    reduce_f<<<(Bb * D2) / 256, 256>>>(bwc, out);

    (void)in_sizes; (void)n_in; (void)out_size;
}

// round 7
// speedup vs baseline: 3.2894x; 1.2271x over previous
#include <cuda_runtime.h>
#include <math.h>

// Problem dims
#define Bb 128
#define Ss 128
#define Nn 196
#define Dd 512
#define D2 1024
#define Tt 12
#define NCH 4          // split-K chunks for comb / write GEMMs
#define N3 1536        // comb GEMM output width (w2 1024 + u 512)

// ---------------- device scratch ----------------
__device__ float g_pp  [2 * Bb * Tt * Dd];   // p partials (z=2)
__device__ float g_P2p [2 * Bb * Tt * Dd];   // P2 partials (z=2)
__device__ float g_cbp [NCH * Bb * N3];      // comb GEMM partials [z][b][1536]
__device__ float g_fpA [NCH * Bb * D2];      // write partials ping
__device__ float g_fpB [NCH * Bb * D2];      // write partials pong
__device__ float g_Wcomb[N3 * Dd];           // [Wra*Wrc^T ; Wcq1]  [1536,512]
__device__ float g_Bcomb[D2 * D2];           // [Wwc ; Wrm@Wwc]     [1024,1024]
__device__ float g_bp2 [Tt * Dd];            // bp @ Wcq2^T
__device__ float g_c   [Bb * Dd];
__device__ float g_m   [Bb * Dd];            // broadcast m0
__device__ float g_mm  [Bb * Dd];            // mm for t=0
__device__ float g_r   [Bb * Dd];
__device__ float g_bias2[Dd];                // brm + Wrm@bwc

// ---------------- helpers ----------------
__device__ __forceinline__ float warp_sum(float v) {
#pragma unroll
    for (int o = 16; o; o >>= 1) v += __shfl_xor_sync(0xffffffffu, v, o);
    return v;
}
__device__ __forceinline__ float warp_max(float v) {
#pragma unroll
    for (int o = 16; o; o >>= 1) v = fmaxf(v, __shfl_xor_sync(0xffffffffu, v, o));
    return v;
}

// ---------------- setup kernels ----------------
__global__ void init_state(const float* __restrict__ ctrl0, const float* __restrict__ mem0) {
    int i = blockIdx.x * blockDim.x + threadIdx.x;
    int d = i & (Dd - 1);
    g_c[i] = ctrl0[d];
    g_m[i] = mem0[d];
}

__global__ void prep_read(const float* __restrict__ Wrm, const float* __restrict__ brm,
                          const float* __restrict__ bwc, const float* __restrict__ mem0) {
    int w = (blockIdx.x * blockDim.x + threadIdx.x) >> 5;
    int lane = threadIdx.x & 31;
    const float* row = Wrm + (size_t)w * Dd;
    float s1 = 0.f, s2 = 0.f;
    for (int d = lane; d < Dd; d += 32) { float x = row[d]; s1 += x * bwc[d]; s2 += x * mem0[d]; }
    s1 = warp_sum(s1); s2 = warp_sum(s2);
    if (lane == 0) g_bias2[w] = brm[w] + s1;
    float mm0 = brm[w] + s2;
    for (int b = lane; b < Bb; b += 32) g_mm[b * Dd + w] = mm0;
}

// Wcomb rows 0..1023: Wcomb[n*512+k] = Wra[k]*Wrc[k*1024+n]  (tiled transpose)
__global__ void prep_wcomb_t(const float* __restrict__ Wrc, const float* __restrict__ Wra) {
    __shared__ float tile[32][33];
    int n0 = blockIdx.x * 32, k0 = blockIdx.y * 32;
    int tx = threadIdx.x & 31, ty = threadIdx.x >> 5;     // 8 rows
#pragma unroll
    for (int i = 0; i < 4; i++) {
        int k = k0 + ty + i * 8;
        tile[ty + i * 8][tx] = Wra[k] * Wrc[(size_t)k * D2 + n0 + tx];
    }
    __syncthreads();
#pragma unroll
    for (int i = 0; i < 4; i++) {
        int n = n0 + ty + i * 8;
        g_Wcomb[(size_t)n * Dd + k0 + tx] = tile[tx][ty + i * 8];
    }
}

// Wcomb rows 1024..1535: copy Wcq first-half columns (Wcq1)
__global__ void prep_wcomb_c(const float* __restrict__ Wcq) {
    int idx = blockIdx.x * blockDim.x + threadIdx.x;   // 0..262143
    int r = idx >> 9, k = idx & 511;
    g_Wcomb[(size_t)(D2 + r) * Dd + k] = Wcq[(size_t)r * D2 + k];
}

// bp2[t,d] = dot(bp[t,:], Wcq2[d,:])
__global__ void prep_bp2(const float* __restrict__ bp, const float* __restrict__ Wcq) {
    int gw = (blockIdx.x * blockDim.x + threadIdx.x) >> 5;   // 0..6143
    int lane = threadIdx.x & 31;
    int t = gw >> 9, d = gw & 511;
    float s = 0.f;
    for (int j = lane; j < Dd; j += 32) s += bp[t * Dd + j] * Wcq[(size_t)d * D2 + Dd + j];
    s = warp_sum(s);
    if (lane == 0) g_bp2[t * Dd + d] = s;
}

// ---------------- split-K GEMM with multi-partial A loads ----------------
// C[M,N] = concat(A0,A1)[M,K] * B^T (+bias).  B(n,k) = Bm[n*strideN + k*strideK].
// A0/A1 may themselves be split-K partial sums: aXsum partials at stride aXpstride,
// a1bias added to the A1 half. BM=64,BN=64,BK=16, 256 thr, 4x4/thread, LDS.128.
__global__ __launch_bounds__(256) void gemm_sk(
    const float* __restrict__ A0, int lda0, int K0, int a0sum, int a0pstride,
    const float* __restrict__ A1, int lda1, int a1sum, int a1pstride,
    const float* __restrict__ a1bias,
    const float* __restrict__ Bm, int strideN, int strideK,
    const float* __restrict__ bias,
    float* __restrict__ Cfin, int ldc,
    float* __restrict__ Part,
    int K)
{
    __shared__ __align__(16) float As[16][68];
    __shared__ __align__(16) float Bs[16][68];
    const int tid = threadIdx.x;
    const int ty = tid >> 4;            // 0..15
    const int tx = tid & 15;            // 0..15
    const int bm = blockIdx.y * 64;
    const int bn = blockIdx.x * 64;
    const int N  = gridDim.x * 64;
    const int kchunk = K / gridDim.z;
    const int kbeg = blockIdx.z * kchunk;
    const int kend = kbeg + kchunk;

    const int aRow = tid >> 2, aKq = tid & 3;
    const int bKk = tid >> 4, bNx = tid & 15;
    const bool nt = (strideK == 1);

    float acc[4][4] = {};
    float4 ra, rb;

    auto loadA = [&](int gk) -> float4 {
        float4 v;
        if (gk < K0) {
            const float* s = A0 + (size_t)(bm + aRow) * lda0 + gk;
            v = *(const float4*)s;
            for (int z = 1; z < a0sum; z++) {
                float4 x = *(const float4*)(s + (size_t)z * a0pstride);
                v.x += x.x; v.y += x.y; v.z += x.z; v.w += x.w;
            }
        } else {
            int g2 = gk - K0;
            const float* s = A1 + (size_t)(bm + aRow) * lda1 + g2;
            v = *(const float4*)s;
            for (int z = 1; z < a1sum; z++) {
                float4 x = *(const float4*)(s + (size_t)z * a1pstride);
                v.x += x.x; v.y += x.y; v.z += x.z; v.w += x.w;
            }
            if (a1bias) {
                float4 bb = *(const float4*)(a1bias + g2);
                v.x += bb.x; v.y += bb.y; v.z += bb.z; v.w += bb.w;
            }
        }
        return v;
    };

    // prologue
    ra = loadA(kbeg + aKq * 4);
    if (nt)  rb = *(const float4*)(Bm + (size_t)(bn + aRow) * strideN + kbeg + aKq * 4);
    else     rb = *(const float4*)(Bm + (size_t)(kbeg + bKk) * strideK + bn + bNx * 4);

    for (int k0 = kbeg; k0 < kend; k0 += 16) {
        As[aKq * 4 + 0][aRow] = ra.x;
        As[aKq * 4 + 1][aRow] = ra.y;
        As[aKq * 4 + 2][aRow] = ra.z;
        As[aKq * 4 + 3][aRow] = ra.w;
        if (nt) {
            Bs[aKq * 4 + 0][aRow] = rb.x;
            Bs[aKq * 4 + 1][aRow] = rb.y;
            Bs[aKq * 4 + 2][aRow] = rb.z;
            Bs[aKq * 4 + 3][aRow] = rb.w;
        } else {
            *(float4*)&Bs[bKk][bNx * 4] = rb;
        }
        __syncthreads();

        if (k0 + 16 < kend) {
            int kn = k0 + 16;
            ra = loadA(kn + aKq * 4);
            if (nt)  rb = *(const float4*)(Bm + (size_t)(bn + aRow) * strideN + kn + aKq * 4);
            else     rb = *(const float4*)(Bm + (size_t)(kn + bKk) * strideK + bn + bNx * 4);
        }

#pragma unroll
        for (int kk = 0; kk < 16; kk++) {
            float4 a = *(const float4*)&As[kk][ty * 4];
            float4 b = *(const float4*)&Bs[kk][tx * 4];
            float av[4] = {a.x, a.y, a.z, a.w};
            float bv[4] = {b.x, b.y, b.z, b.w};
#pragma unroll
            for (int i = 0; i < 4; i++)
#pragma unroll
                for (int j = 0; j < 4; j++) acc[i][j] += av[i] * bv[j];
        }
        __syncthreads();
    }

    if (Part) {
        size_t base = (size_t)blockIdx.z * (size_t)(gridDim.y * 64) * N;
#pragma unroll
        for (int i = 0; i < 4; i++) {
            int m = bm + ty * 4 + i;
            float4 v = make_float4(acc[i][0], acc[i][1], acc[i][2], acc[i][3]);
            *(float4*)&Part[base + (size_t)m * N + bn + tx * 4] = v;
        }
    } else {
        float4 bz = make_float4(0.f, 0.f, 0.f, 0.f);
        if (bias) bz = *(const float4*)(bias + bn + tx * 4);
#pragma unroll
        for (int i = 0; i < 4; i++) {
            int m = bm + ty * 4 + i;
            float4 v = make_float4(acc[i][0] + bz.x, acc[i][1] + bz.y,
                                   acc[i][2] + bz.z, acc[i][3] + bz.w);
            *(float4*)&Cfin[(size_t)m * ldc + bn + tx * 4] = v;
        }
    }
}

// ---------------- ctx attention (reduces comb u-half + P2 partials) -----------
__global__ void attn_ctx(const float* __restrict__ ctx, const float* __restrict__ bcq,
                         const float* __restrict__ Wca, int t) {
    __shared__ __align__(16) float us[Dd];
    __shared__ float sl[Ss];
    __shared__ float red;
    const int b = blockIdx.x;
    const int tid = threadIdx.x;
    const int lane = tid & 31, warp = tid >> 5;

    {
        int o = b * N3 + D2 + tid;                        // u half of comb output
        float v = g_cbp[o] + g_cbp[Bb * N3 + o] + g_cbp[2 * Bb * N3 + o] + g_cbp[3 * Bb * N3 + o];
        int pr = (b * Tt + t) * Dd + tid;
        v += g_P2p[pr] + g_P2p[2 * Bb * Tt * Dd / 2 + pr];   // 2 partials, stride 786432
        v += bcq[tid] + g_bp2[t * Dd + tid];
        us[tid] = v * Wca[tid];
    }
    __syncthreads();

    const float* cb = ctx + (size_t)b * Ss * Dd;
    const float4* us4 = (const float4*)us;
    for (int s = warp; s < Ss; s += 16) {
        const float4* row4 = (const float4*)(cb + (size_t)s * Dd);
        float part = 0.f;
#pragma unroll
        for (int d4 = lane; d4 < Dd / 4; d4 += 32) {
            float4 a = row4[d4], u = us4[d4];
            part += a.x * u.x + a.y * u.y + a.z * u.z + a.w * u.w;
        }
        part = warp_sum(part);
        if (lane == 0) sl[s] = part;
    }
    __syncthreads();
    if (warp == 0) {
        float mx = -1e30f;
        for (int i = lane; i < Ss; i += 32) mx = fmaxf(mx, sl[i]);
        mx = warp_max(mx);
        float sm = 0.f;
        for (int i = lane; i < Ss; i += 32) { float e = __expf(sl[i] - mx); sl[i] = e; sm += e; }
        sm = warp_sum(sm);
        if (lane == 0) red = 1.f / sm;
    }
    __syncthreads();
    const float inv = red;
    float acc = 0.f;
#pragma unroll 8
    for (int s = 0; s < Ss; s++) acc += sl[s] * cb[(size_t)s * Dd + tid];
    g_c[b * Dd + tid] = acc * inv;
}

// ---------------- k attention (reduces comb w2-half; mm from fp or g_mm) ------
__global__ void attn_k(const float* __restrict__ kp, const float* __restrict__ fpm) {
    __shared__ float gs[Dd];
    __shared__ float rw[Nn];
    __shared__ float rw1[Nn];
    __shared__ float red;
    const int b = blockIdx.x;
    const int tid = threadIdx.x;
    const int lane = tid & 31, warp = tid >> 5;

    {
        int oa = b * N3 + tid;
        int ob = oa + Dd;
        float w2a = g_cbp[oa] + g_cbp[Bb * N3 + oa] + g_cbp[2 * Bb * N3 + oa] + g_cbp[3 * Bb * N3 + oa];
        float w2b = g_cbp[ob] + g_cbp[Bb * N3 + ob] + g_cbp[2 * Bb * N3 + ob] + g_cbp[3 * Bb * N3 + ob];
        float mmv;
        if (fpm) {
            int o = b * D2 + Dd + tid;
            mmv = fpm[o] + fpm[Bb * D2 + o] + fpm[2 * Bb * D2 + o] + fpm[3 * Bb * D2 + o]
                + g_bias2[tid];
        } else {
            mmv = g_mm[b * Dd + tid];
        }
        gs[tid] = w2a * mmv + w2b;
    }
    __syncthreads();

    const float* kb = kp + (size_t)b * Dd * Nn;
    {
        int half = tid >> 8;                 // 0 or 1
        int n = tid & 255;
        if (n < Nn) {
            float acc = 0.f;
            int j0 = half * 256;
#pragma unroll 8
            for (int j = j0; j < j0 + 256; j++) acc += gs[j] * kb[(size_t)j * Nn + n];
            (half ? rw1 : rw)[n] = acc;
        }
    }
    __syncthreads();
    if (tid < Nn) rw[tid] += rw1[tid];
    __syncthreads();
    if (warp == 0) {
        float mx = -1e30f;
        for (int i = lane; i < Nn; i += 32) mx = fmaxf(mx, rw[i]);
        mx = warp_max(mx);
        float sm = 0.f;
        for (int i = lane; i < Nn; i += 32) { float e = __expf(rw[i] - mx); rw[i] = e; sm += e; }
        sm = warp_sum(sm);
        if (lane == 0) red = 1.f / sm;
    }
    __syncthreads();
    const float inv = red;
    for (int d = warp; d < Dd; d += 16) {
        const float* row = kb + (size_t)d * Nn;
        float part = 0.f;
        for (int n = lane; n < Nn; n += 32) part += rw[n] * row[n];
        part = warp_sum(part);
        if (lane == 0) g_r[b * Dd + d] = part * inv;
    }
}

// ---------------- final output reduce ----------------
__global__ void reduce_out(const float* __restrict__ fpL, const float* __restrict__ bwc,
                           float* __restrict__ out) {
    int idx = blockIdx.x * blockDim.x + threadIdx.x;   // 0..65535
    int b = idx >> 9, j = idx & 511;
    int o = b * D2 + j;
    out[idx] = fpL[o] + fpL[Bb * D2 + o] + fpL[2 * Bb * D2 + o] + fpL[3 * Bb * D2 + o] + bwc[j];
}

// ---------------- host ----------------
extern "C" void kernel_launch(void* const* d_in, const int* in_sizes, int n_in,
                              void* d_out, int out_size)
{
    const float* ctx  = (const float*)d_in[0];
    const float* q    = (const float*)d_in[1];
    const float* kten = (const float*)d_in[2];
    const float* mem0 = (const float*)d_in[3];
    const float* ctrl0= (const float*)d_in[4];
    const float* Wp   = (const float*)d_in[5];
    const float* bp   = (const float*)d_in[6];
    const float* Wcq  = (const float*)d_in[7];
    const float* bcq  = (const float*)d_in[8];
    const float* Wca  = (const float*)d_in[9];
    const float* Wrm  = (const float*)d_in[11];
    const float* brm  = (const float*)d_in[12];
    const float* Wrc  = (const float*)d_in[13];
    const float* Wra  = (const float*)d_in[15];
    const float* Wwc  = (const float*)d_in[17];
    const float* bwc  = (const float*)d_in[18];
    float* out = (float*)d_out;

    float *pp_, *P2p_, *cbp_, *fpA_, *fpB_, *Wc_, *Bc_, *c_, *m_, *r_;
    cudaGetSymbolAddress((void**)&pp_,  g_pp);
    cudaGetSymbolAddress((void**)&P2p_, g_P2p);
    cudaGetSymbolAddress((void**)&cbp_, g_cbp);
    cudaGetSymbolAddress((void**)&fpA_, g_fpA);
    cudaGetSymbolAddress((void**)&fpB_, g_fpB);
    cudaGetSymbolAddress((void**)&Wc_,  g_Wcomb);
    cudaGetSymbolAddress((void**)&Bc_,  g_Bcomb);
    cudaGetSymbolAddress((void**)&c_,   g_c);
    cudaGetSymbolAddress((void**)&m_,   g_m);
    cudaGetSymbolAddress((void**)&r_,   g_r);

    // --- setup ---
    init_state<<<(Bb * Dd) / 256, 256>>>(ctrl0, mem0);
    prep_read<<<64, 256>>>(Wrm, brm, bwc, mem0);
    prep_wcomb_t<<<dim3(32, 16), 256>>>(Wrc, Wra);
    prep_wcomb_c<<<1024, 256>>>(Wcq);
    prep_bp2<<<768, 256>>>(bp, Wcq);
    cudaMemcpyAsync(Bc_, Wwc, (size_t)Dd * D2 * sizeof(float), cudaMemcpyDeviceToDevice, 0);
    // Bcomb bottom = Wrm @ Wwc  (M=512, N=1024, K=512, NN)
    gemm_sk<<<dim3(16, 8, 1), 256>>>(Wrm, Dd, Dd, 1, 0, nullptr, 0, 1, 0, nullptr,
                                     Wwc, 1, D2, nullptr,
                                     Bc_ + (size_t)Dd * D2, D2, nullptr, Dd);
    // p partials: q @ Wp^T  (M=128, N=6144, K=1024, z=2)
    gemm_sk<<<dim3(96, 2, 2), 256>>>(q, D2, D2, 1, 0, nullptr, 0, 1, 0, nullptr,
                                     Wp, D2, 1, nullptr,
                                     nullptr, 0, pp_, D2);
    // P2 partials: p(sum2, viewed [1536,512]) @ Wcq2^T  (M=1536, N=512, K=512, z=2)
    gemm_sk<<<dim3(8, 24, 2), 256>>>(pp_, Dd, Dd, 2, Bb * Tt * Dd, nullptr, 0, 1, 0, nullptr,
                                     Wcq + Dd, D2, 1, nullptr,
                                     nullptr, 0, P2p_, Dd);
    // comb on c0 -> u_0 (w2 half unused)
    gemm_sk<<<dim3(24, 2, NCH), 256>>>(c_, Dd, Dd, 1, 0, nullptr, 0, 1, 0, nullptr,
                                       Wc_, Dd, 1, nullptr,
                                       nullptr, 0, cbp_, Dd);

    for (int t = 0; t < Tt; t++) {
        const float* fp_prev = (t == 0) ? nullptr : ((t & 1) ? fpA_ : fpB_);
        float* fp_cur = (t & 1) ? fpB_ : fpA_;

        attn_ctx<<<Bb, Dd>>>(ctx, bcq, Wca, t);
        // comb: c @ Wcomb^T -> [w2_t ; u_{t+1}]  (M=128, N=1536, K=512, z=4)
        gemm_sk<<<dim3(24, 2, NCH), 256>>>(c_, Dd, Dd, 1, 0, nullptr, 0, 1, 0, nullptr,
                                           Wc_, Dd, 1, nullptr,
                                           nullptr, 0, cbp_, Dd);
        attn_k<<<Bb, Dd>>>(kten, fp_prev);
        // write: concat(r, m) @ Bcomb^T  (M=128, N=1024, K=1024, z=4)
        if (t == 0) {
            gemm_sk<<<dim3(16, 2, NCH), 256>>>(r_, Dd, Dd, 1, 0,
                                               m_, Dd, 1, 0, nullptr,
                                               Bc_, D2, 1, nullptr,
                                               nullptr, 0, fp_cur, D2);
        } else {
            gemm_sk<<<dim3(16, 2, NCH), 256>>>(r_, Dd, Dd, 1, 0,
                                               (float*)fp_prev, D2, NCH, Bb * D2, bwc,
                                               Bc_, D2, 1, nullptr,
                                               nullptr, 0, fp_cur, D2);
        }
    }
    // final m -> out  (last write went to fpB_ since Tt even -> t=11 odd -> fpB_)
    reduce_out<<<(Bb * Dd) / 256, 256>>>(fpB_, bwc, out);

    (void)in_sizes; (void)n_in; (void)out_size;
}